// round 2
// baseline (speedup 1.0000x reference)
#include <cuda_runtime.h>

#define IMG 256
#define NPIX (IMG*IMG)
#define V 182
#define BATCH 64
#define BPB 8                      // blocks per batch
#define THREADS 512
#define PIX_PER_BLOCK (NPIX/BPB)   // 8192

__device__ float g_sums[BATCH*V];
__device__ int   g_cnt[V];

__global__ void k_zero() {
    int i = blockIdx.x*blockDim.x + threadIdx.x;
    if (i < BATCH*V) g_sums[i] = 0.f;
    if (i < V) g_cnt[i] = 0;
}

__device__ __forceinline__ int radius_of(int p) {
    int i = p >> 8, j = p & 255;
    int di = i - 128, dj = j - 128;
    int s = di*di + dj*dj;
    float f = __fsqrt_rn((float)s);   // correctly rounded regardless of fast-math
    int r = (int)f;
    if ((r+1)*(r+1) <= s) r++;        // exact integer isqrt correction
    if (r*r > s) r--;
    return r;
}

__global__ __launch_bounds__(THREADS) void k_hist(const float* __restrict__ x) {
    __shared__ float sh[V];
    __shared__ int   shc[V];
    int b     = blockIdx.x / BPB;
    int chunk = blockIdx.x % BPB;
    bool do_cnt = (b == 0);

    for (int v = threadIdx.x; v < V; v += THREADS) { sh[v] = 0.f; shc[v] = 0; }
    __syncthreads();

    const float* __restrict__ rp = x + (size_t)b * 3 * NPIX;
    const float* __restrict__ gp = rp + NPIX;
    const float* __restrict__ bp = gp + NPIX;

    int base = chunk * PIX_PER_BLOCK;
    #pragma unroll
    for (int it = 0; it < PIX_PER_BLOCK/(THREADS*4); ++it) {
        int p4 = base + (it*THREADS + threadIdx.x) * 4;
        float4 rr = *(const float4*)(rp + p4);
        float4 gg = *(const float4*)(gp + p4);
        float4 bb = *(const float4*)(bp + p4);

        float m0 = 20.f*(0.299f*rr.x + 0.587f*gg.x + 0.114f*bb.x);
        float m1 = 20.f*(0.299f*rr.y + 0.587f*gg.y + 0.114f*bb.y);
        float m2 = 20.f*(0.299f*rr.z + 0.587f*gg.z + 0.114f*bb.z);
        float m3 = 20.f*(0.299f*rr.w + 0.587f*gg.w + 0.114f*bb.w);

        int r0 = radius_of(p4+0);
        int r1 = radius_of(p4+1);
        int r2 = radius_of(p4+2);
        int r3 = radius_of(p4+3);

        atomicAdd(&sh[r0], m0);
        atomicAdd(&sh[r1], m1);
        atomicAdd(&sh[r2], m2);
        atomicAdd(&sh[r3], m3);
        if (do_cnt) {
            atomicAdd(&shc[r0], 1);
            atomicAdd(&shc[r1], 1);
            atomicAdd(&shc[r2], 1);
            atomicAdd(&shc[r3], 1);
        }
    }
    __syncthreads();

    for (int v = threadIdx.x; v < V; v += THREADS) {
        if (sh[v] != 0.f) atomicAdd(&g_sums[b*V + v], sh[v]);
        else              atomicAdd(&g_sums[b*V + v], 0.f);  // keep deterministic write pattern simple
        if (do_cnt && shc[v]) atomicAdd(&g_cnt[v], shc[v]);
    }
}

__global__ void k_final(float* __restrict__ out) {
    __shared__ float smin[32], smax[32];
    int tid = threadIdx.x;
    float lmin =  __int_as_float(0x7f800000);   // +inf
    float lmax = -__int_as_float(0x7f800000);   // -inf
    for (int i = tid; i < BATCH*V; i += blockDim.x) {
        float p = g_sums[i] / (float)g_cnt[i % V];
        lmin = fminf(lmin, p);
        lmax = fmaxf(lmax, p);
    }
    #pragma unroll
    for (int o = 16; o; o >>= 1) {
        lmin = fminf(lmin, __shfl_xor_sync(0xFFFFFFFFu, lmin, o));
        lmax = fmaxf(lmax, __shfl_xor_sync(0xFFFFFFFFu, lmax, o));
    }
    if ((tid & 31) == 0) { smin[tid>>5] = lmin; smax[tid>>5] = lmax; }
    __syncthreads();
    int nw = blockDim.x >> 5;
    if (tid < 32) {
        lmin = (tid < nw) ? smin[tid] :  __int_as_float(0x7f800000);
        lmax = (tid < nw) ? smax[tid] : -__int_as_float(0x7f800000);
        #pragma unroll
        for (int o = 16; o; o >>= 1) {
            lmin = fminf(lmin, __shfl_xor_sync(0xFFFFFFFFu, lmin, o));
            lmax = fmaxf(lmax, __shfl_xor_sync(0xFFFFFFFFu, lmax, o));
        }
        if (tid == 0) { smin[0] = lmin; smax[0] = lmax; }
    }
    __syncthreads();
    float mn = smin[0];
    float scale = 1.f / (smax[0] - mn);
    for (int i = tid; i < BATCH*V; i += blockDim.x) {
        float p = g_sums[i] / (float)g_cnt[i % V];
        out[i] = (p - mn) * scale;
    }
}

extern "C" void kernel_launch(void* const* d_in, const int* in_sizes, int n_in,
                              void* d_out, int out_size) {
    const float* x = (const float*)d_in[0];
    float* out = (float*)d_out;
    (void)in_sizes; (void)n_in; (void)out_size;

    k_zero<<<(BATCH*V + 255)/256, 256>>>();
    k_hist<<<BATCH*BPB, THREADS>>>(x);
    k_final<<<1, 1024>>>(out);
}

// round 3
// speedup vs baseline: 1.2188x; 1.2188x over previous
#include <cuda_runtime.h>

#define IMG 256
#define NPIX (IMG*IMG)
#define V 182
#define VPAD 192
#define BATCH 64
#define BPB 8                      // blocks per batch
#define THREADS 512
#define PIX_PER_BLOCK (NPIX/BPB)   // 8192
#define NBLK (BATCH*BPB)           // 512

// ---------------- compile-time radius + count tables ----------------
struct Tables {
    unsigned char r[NPIX];
    int cnt[V];
};

constexpr Tables make_tables() {
    Tables t{};
    for (int i = 0; i < IMG; ++i) {
        int di = i - 128;
        int s0 = di*di + 128*128;
        int r = 0;
        while ((r+1)*(r+1) <= s0) ++r;      // seed floor-isqrt for j=0
        for (int j = 0; j < IMG; ++j) {
            int dj = j - 128;
            int s = di*di + dj*dj;
            while ((r+1)*(r+1) <= s) ++r;   // |delta r| <= 1 per j step
            while (r > 0 && r*r > s) --r;
            t.r[i*IMG + j] = (unsigned char)r;
            t.cnt[r] += 1;
        }
    }
    return t;
}

__device__ const Tables g_tab = make_tables();

// per-block partial sums; fully overwritten every launch (no zero kernel needed)
__device__ float g_part[NBLK * VPAD];

// ---------------- histogram kernel ----------------
__global__ __launch_bounds__(THREADS) void k_hist(const float* __restrict__ x) {
    __shared__ float sh[V];

    int b     = blockIdx.x / BPB;
    int chunk = blockIdx.x % BPB;

    for (int v = threadIdx.x; v < V; v += THREADS) sh[v] = 0.f;
    __syncthreads();

    const float* __restrict__ rp = x + (size_t)b * 3 * NPIX;
    const float* __restrict__ gp = rp + NPIX;
    const float* __restrict__ bp = gp + NPIX;
    const unsigned char* __restrict__ rt = g_tab.r;

    int base = chunk * PIX_PER_BLOCK;
    #pragma unroll
    for (int it = 0; it < PIX_PER_BLOCK/(THREADS*4); ++it) {
        int p4 = base + (it*THREADS + threadIdx.x) * 4;
        float4 rr = *(const float4*)(rp + p4);
        float4 gg = *(const float4*)(gp + p4);
        float4 bb = *(const float4*)(bp + p4);
        uchar4 rq = *(const uchar4*)(rt + p4);

        float m0 = 20.f*(0.299f*rr.x + 0.587f*gg.x + 0.114f*bb.x);
        float m1 = 20.f*(0.299f*rr.y + 0.587f*gg.y + 0.114f*bb.y);
        float m2 = 20.f*(0.299f*rr.z + 0.587f*gg.z + 0.114f*bb.z);
        float m3 = 20.f*(0.299f*rr.w + 0.587f*gg.w + 0.114f*bb.w);

        // merge equal-radius neighbors before touching shared atomics
        float v = m0; unsigned cr = rq.x;
        if (rq.y == cr) { v += m1; } else { atomicAdd(&sh[cr], v); cr = rq.y; v = m1; }
        if (rq.z == cr) { v += m2; } else { atomicAdd(&sh[cr], v); cr = rq.z; v = m2; }
        if (rq.w == cr) { v += m3; } else { atomicAdd(&sh[cr], v); cr = rq.w; v = m3; }
        atomicAdd(&sh[cr], v);
    }
    __syncthreads();

    float* dst = g_part + (size_t)blockIdx.x * VPAD;
    for (int v = threadIdx.x; v < V; v += THREADS) dst[v] = sh[v];
}

// ---------------- reduce + normalize kernel ----------------
__global__ __launch_bounds__(1024) void k_final(float* __restrict__ out) {
    __shared__ float prof[BATCH*V];   // 46592 B
    __shared__ float invc[V];
    __shared__ float smin[32], smax[32];

    int tid = threadIdx.x;
    if (tid < V) invc[tid] = 1.f / (float)g_tab.cnt[tid];
    __syncthreads();

    float lmin =  __int_as_float(0x7f800000);
    float lmax = -__int_as_float(0x7f800000);

    for (int i = tid; i < BATCH*V; i += 1024) {
        int b = i / V;
        int v = i - b * V;
        const float* p = g_part + (size_t)(b * BPB) * VPAD + v;
        float s = 0.f;
        #pragma unroll
        for (int c = 0; c < BPB; ++c) s += p[c * VPAD];
        float pr = s * invc[v];
        prof[i] = pr;
        lmin = fminf(lmin, pr);
        lmax = fmaxf(lmax, pr);
    }

    #pragma unroll
    for (int o = 16; o; o >>= 1) {
        lmin = fminf(lmin, __shfl_xor_sync(0xFFFFFFFFu, lmin, o));
        lmax = fmaxf(lmax, __shfl_xor_sync(0xFFFFFFFFu, lmax, o));
    }
    if ((tid & 31) == 0) { smin[tid>>5] = lmin; smax[tid>>5] = lmax; }
    __syncthreads();
    if (tid < 32) {
        lmin = (tid < 32) ? smin[tid] :  __int_as_float(0x7f800000);
        lmax = (tid < 32) ? smax[tid] : -__int_as_float(0x7f800000);
        #pragma unroll
        for (int o = 16; o; o >>= 1) {
            lmin = fminf(lmin, __shfl_xor_sync(0xFFFFFFFFu, lmin, o));
            lmax = fmaxf(lmax, __shfl_xor_sync(0xFFFFFFFFu, lmax, o));
        }
        if (tid == 0) { smin[0] = lmin; smax[0] = lmax; }
    }
    __syncthreads();

    float mn = smin[0];
    float scale = 1.f / (smax[0] - mn);
    for (int i = tid; i < BATCH*V; i += 1024)
        out[i] = (prof[i] - mn) * scale;
}

extern "C" void kernel_launch(void* const* d_in, const int* in_sizes, int n_in,
                              void* d_out, int out_size) {
    const float* x = (const float*)d_in[0];
    float* out = (float*)d_out;
    (void)in_sizes; (void)n_in; (void)out_size;

    k_hist<<<NBLK, THREADS>>>(x);
    k_final<<<1, 1024>>>(out);
}